// round 5
// baseline (speedup 1.0000x reference)
#include <cuda_runtime.h>
#include <cuda_bf16.h>

#define N_NODES 50000
#define N_EDGES 800000
#define IN_DIM  128
#define HD      128   // N_HEAD * OUT_DIM
#define NHEAD   4
#define IN_E    16

#define SCAN_BS 512
#define NBLK_SCAN ((N_NODES + SCAN_BS - 1) / SCAN_BS)   // 98

// ---------------- scratch (__device__ globals; alloc-free rule) ----------------
__device__ float g_featn[(size_t)N_NODES * HD];   // projected node features [N,128]
__device__ float g_el[N_NODES * NHEAD];
__device__ float g_er[N_NODES * NHEAD];
__device__ float g_lgs[(size_t)N_EDGES * NHEAD];  // leaky-relu logits, CSR (dst-sorted) order
__device__ int   g_srcs[N_EDGES];                 // src node per CSR slot
__device__ int   g_cnt[N_NODES];                  // in-degree histogram (zeroed by k_node)
__device__ int   g_off[N_NODES + 1];              // CSR offsets
__device__ int   g_cur[N_NODES];                  // scatter cursors
__device__ int   g_tilectr;                       // scan tile counter (zeroed by k_gemm)
__device__ unsigned long long g_tstat[NBLK_SCAN]; // scan tile status (zeroed by k_gemm)

// ---------------- f32x2 packed-FMA helpers (sm_100+) ----------------
typedef unsigned long long ull;
__device__ __forceinline__ void ffma2(ull& d, ull a, ull b) {
    asm("fma.rn.f32x2 %0, %1, %2, %0;" : "+l"(d) : "l"(a), "l"(b));
}
__device__ __forceinline__ ull pack2(float v) {
    ull r; asm("mov.b64 %0, {%1, %1};" : "=l"(r) : "f"(v)); return r;
}

// ---------------- K0: SGEMM + fused histogram + fused el/er epilogue ----------------
// 256 threads; block tile 128 nodes x 128 outs; thread tile 8x8.
#define GSTR 132
__global__ void k_gemm(const float* __restrict__ x, const float* __restrict__ W,
                       const float* __restrict__ al, const float* __restrict__ ar,
                       const int* __restrict__ dst) {
    extern __shared__ float sm[];
    float* Wsm = sm;                    // [k*132 + out]
    float* Xs  = sm + IN_DIM * GSTR;    // [k*132 + n_local]
    int tid = threadIdx.x;
    int base = blockIdx.x * 128;
    int gid  = blockIdx.x * 256 + tid;

    // zero scan state for this run (consumed by k_scan, next kernel)
    if (gid == 0) g_tilectr = 0;
    if (gid < NBLK_SCAN) g_tstat[gid] = 0ull;
    // fused in-degree histogram (g_cnt zeroed by previous run's k_node / loader)
    for (int e = gid; e < N_EDGES; e += gridDim.x * 256)
        atomicAdd(&g_cnt[dst[e]], 1);

    for (int i = tid; i < 128 * 128; i += 256) {
        int out = i >> 7, k = i & 127;
        Wsm[k * GSTR + out] = W[i];
    }
    for (int i = tid; i < 128 * 128; i += 256) {
        int n = i >> 7, k = i & 127;
        int gn = base + n;
        Xs[k * GSTR + n] = (gn < N_NODES) ? x[(size_t)gn * IN_DIM + k] : 0.0f;
    }
    __syncthreads();

    int ty = tid >> 4, tx = tid & 15;         // ty: 8 nodes, tx: 8 outs
    int n0 = ty * 8, c0 = tx * 8;
    ull acc[8][4];
    #pragma unroll
    for (int j = 0; j < 8; j++)
        #pragma unroll
        for (int p = 0; p < 4; p++) acc[j][p] = 0ull;

    #pragma unroll 4
    for (int k = 0; k < IN_DIM; k++) {
        const float* xr = Xs  + k * GSTR + n0;
        const float* wr = Wsm + k * GSTR + c0;
        ulonglong2 w0 = *(const ulonglong2*)(wr);
        ulonglong2 w1 = *(const ulonglong2*)(wr + 4);
        float4 xa = *(const float4*)(xr);
        float4 xb = *(const float4*)(xr + 4);
        float xv[8] = {xa.x, xa.y, xa.z, xa.w, xb.x, xb.y, xb.z, xb.w};
        #pragma unroll
        for (int j = 0; j < 8; j++) {
            ull px = pack2(xv[j]);
            ffma2(acc[j][0], px, w0.x);
            ffma2(acc[j][1], px, w0.y);
            ffma2(acc[j][2], px, w1.x);
            ffma2(acc[j][3], px, w1.y);
        }
    }
    #pragma unroll
    for (int j = 0; j < 8; j++) {
        int node = base + n0 + j;
        if (node < N_NODES) {
            ull* o = (ull*)(g_featn + (size_t)node * HD + c0);
            o[0] = acc[j][0]; o[1] = acc[j][1]; o[2] = acc[j][2]; o[3] = acc[j][3];
        }
    }

    // ---- fused attention epilogue: el[n,h], er[n,h] from register accumulators ----
    __syncthreads();                           // smem reusable now
    float* sel = sm;                           // [128 nodes][16 tx]
    float* ser = sm + 128 * 16;
    float4 ala = *(const float4*)(al + c0);
    float4 alb = *(const float4*)(al + c0 + 4);
    float4 ara = *(const float4*)(ar + c0);
    float4 arb = *(const float4*)(ar + c0 + 4);
    #pragma unroll
    for (int j = 0; j < 8; j++) {
        float2 f0 = *(float2*)&acc[j][0];
        float2 f1 = *(float2*)&acc[j][1];
        float2 f2 = *(float2*)&acc[j][2];
        float2 f3 = *(float2*)&acc[j][3];
        float pel = f0.x*ala.x + f0.y*ala.y + f1.x*ala.z + f1.y*ala.w
                  + f2.x*alb.x + f2.y*alb.y + f3.x*alb.z + f3.y*alb.w;
        float per = f0.x*ara.x + f0.y*ara.y + f1.x*ara.z + f1.y*ara.w
                  + f2.x*arb.x + f2.y*arb.y + f3.x*arb.z + f3.y*arb.w;
        sel[(n0 + j) * 16 + tx] = pel;
        ser[(n0 + j) * 16 + tx] = per;
    }
    __syncthreads();
    // 512 (node,head) pairs; each thread reduces 2 of them (4 partials each)
    for (int id = tid; id < 512; id += 256) {
        int node = id >> 2, h = id & 3;
        float s1 = 0.f, s2 = 0.f;
        #pragma unroll
        for (int q = 0; q < 4; q++) {
            s1 += sel[node * 16 + h * 4 + q];
            s2 += ser[node * 16 + h * 4 + q];
        }
        int gn = base + node;
        if (gn < N_NODES) {
            g_el[gn * NHEAD + h] = s1;
            g_er[gn * NHEAD + h] = s2;
        }
    }
}

// ---------------- K1: single-pass decoupled-lookback exclusive scan ----------------
// status word: high32 flag (0=empty,1=aggregate,2=inclusive prefix), low32 value
__global__ void k_scan() {
    __shared__ int stile;
    __shared__ int swarp[16];
    __shared__ int sprefix;
    int t = threadIdx.x;
    if (t == 0) stile = atomicAdd(&g_tilectr, 1);
    __syncthreads();
    int tile = stile;
    int i = tile * SCAN_BS + t;
    int v = (i < N_NODES) ? g_cnt[i] : 0;

    int lane = t & 31, wid = t >> 5;
    int xv = v;
    #pragma unroll
    for (int o = 1; o < 32; o <<= 1) {
        int u = __shfl_up_sync(0xffffffffu, xv, o);
        if (lane >= o) xv += u;
    }
    if (lane == 31) swarp[wid] = xv;
    __syncthreads();
    if (wid == 0) {
        int y = (lane < 16) ? swarp[lane] : 0;
        #pragma unroll
        for (int o = 1; o < 16; o <<= 1) {
            int u = __shfl_up_sync(0xffffffffu, y, o);
            if (lane >= o) y += u;
        }
        if (lane < 16) swarp[lane] = y;
    }
    __syncthreads();
    int incl = xv + (wid ? swarp[wid - 1] : 0);
    int total = swarp[15];

    if (t == 0) {
        if (tile == 0) {
            __threadfence();
            atomicExch(&g_tstat[0], (2ull << 32) | (unsigned)total);
            sprefix = 0;
        } else {
            __threadfence();
            atomicExch(&g_tstat[tile], (1ull << 32) | (unsigned)total);
            int excl = 0;
            for (int tb = tile - 1; tb >= 0;) {
                unsigned long long s;
                do { s = atomicAdd(&g_tstat[tb], 0ull); } while ((s >> 32) == 0ull);
                excl += (int)(unsigned)s;
                if ((s >> 32) == 2ull) break;
                tb--;
            }
            __threadfence();
            atomicExch(&g_tstat[tile], (2ull << 32) | (unsigned)(excl + total));
            sprefix = excl;
        }
    }
    __syncthreads();
    int pre = sprefix;
    if (i < N_NODES) {
        int off = pre + incl - v;
        g_off[i] = off;
        g_cur[i] = off;
    }
    if (i == N_NODES - 1) g_off[N_NODES] = pre + incl;   // == N_EDGES
}

// ---------------- K2: edge logits + leaky relu, written directly in CSR order ----------------
__global__ void k_logit(const float* __restrict__ fe, const int* __restrict__ src,
                        const int* __restrict__ dst, const float* __restrict__ ae) {
    __shared__ float aesm[NHEAD * IN_E];
    if (threadIdx.x < NHEAD * IN_E) aesm[threadIdx.x] = ae[threadIdx.x];
    __syncthreads();
    int e = blockIdx.x * blockDim.x + threadIdx.x;
    if (e >= N_EDGES) return;
    int s = src[e], d = dst[e];

    const float4* fr = (const float4*)(fe + (size_t)e * IN_E);
    float4 f0 = fr[0], f1 = fr[1], f2 = fr[2], f3 = fr[3];
    float4 elv = *(const float4*)(g_el + s * NHEAD);
    float4 erv = *(const float4*)(g_er + d * NHEAD);
    float els[4] = {elv.x, elv.y, elv.z, elv.w};
    float ers[4] = {erv.x, erv.y, erv.z, erv.w};

    float lg[4];
    #pragma unroll
    for (int h = 0; h < NHEAD; h++) {
        const float* a = aesm + h * IN_E;
        float ee = f0.x*a[0]  + f0.y*a[1]  + f0.z*a[2]  + f0.w*a[3]
                 + f1.x*a[4]  + f1.y*a[5]  + f1.z*a[6]  + f1.w*a[7]
                 + f2.x*a[8]  + f2.y*a[9]  + f2.z*a[10] + f2.w*a[11]
                 + f3.x*a[12] + f3.y*a[13] + f3.z*a[14] + f3.w*a[15];
        float v = els[h] + ers[h] + ee;
        lg[h] = v > 0.0f ? v : 0.2f * v;                // leaky relu 0.2
    }
    int pos = atomicAdd(&g_cur[d], 1);                  // CSR slot
    ((float4*)g_lgs)[pos] = make_float4(lg[0], lg[1], lg[2], lg[3]);
    g_srcs[pos] = s;
}

// ---------------- K3: per-dst-node softmax + weighted aggregate (PROFILED SLOT) ----------------
__global__ void k_node(float* __restrict__ out) {
    int w = (blockIdx.x * blockDim.x + threadIdx.x) >> 5;
    if (w >= N_NODES) return;
    int lane = threadIdx.x & 31;
    int c = lane * 4, h = lane >> 3;
    float* orow = out + (size_t)w * HD + c;

    if (lane == 0) g_cnt[w] = 0;                        // restore invariant for next run

    int beg = g_off[w], end = g_off[w + 1];
    if (beg == end) {                                   // zero-degree node
        *(float4*)orow = make_float4(0.f, 0.f, 0.f, 0.f);
        return;
    }
    const float NEG = -3.4e38f;
    // pass 1: per-head max (coalesced sequential float4 loads)
    float4 mx = make_float4(NEG, NEG, NEG, NEG);
    for (int p = beg + lane; p < end; p += 32) {
        float4 lg = ((const float4*)g_lgs)[p];
        mx.x = fmaxf(mx.x, lg.x); mx.y = fmaxf(mx.y, lg.y);
        mx.z = fmaxf(mx.z, lg.z); mx.w = fmaxf(mx.w, lg.w);
    }
    #pragma unroll
    for (int o = 16; o; o >>= 1) {
        mx.x = fmaxf(mx.x, __shfl_xor_sync(0xffffffffu, mx.x, o));
        mx.y = fmaxf(mx.y, __shfl_xor_sync(0xffffffffu, mx.y, o));
        mx.z = fmaxf(mx.z, __shfl_xor_sync(0xffffffffu, mx.z, o));
        mx.w = fmaxf(mx.w, __shfl_xor_sync(0xffffffffu, mx.w, o));
    }
    float mh = (h == 0) ? mx.x : (h == 1) ? mx.y : (h == 2) ? mx.z : mx.w;

    // merged pass: sum of exp and sum of exp * gathered feature
    float sh = 0.0f;
    float4 acc = make_float4(0.f, 0.f, 0.f, 0.f);
    int p0 = beg;
    for (; p0 + 32 <= end; p0 += 32) {
        int sv = g_srcs[p0 + lane];
        #pragma unroll 8
        for (int j = 0; j < 32; j++) {
            int sn = __shfl_sync(0xffffffffu, sv, j);
            float lgv = g_lgs[(size_t)(p0 + j) * NHEAD + h];
            float a = __expf(lgv - mh);
            sh += a;
            float4 f = *(const float4*)(g_featn + (size_t)sn * HD + c);
            acc.x += a * f.x; acc.y += a * f.y; acc.z += a * f.z; acc.w += a * f.w;
        }
    }
    if (p0 < end) {
        int rem = end - p0;
        int sv = (lane < rem) ? g_srcs[p0 + lane] : 0;
        for (int j = 0; j < rem; j++) {
            int sn = __shfl_sync(0xffffffffu, sv, j);
            float lgv = g_lgs[(size_t)(p0 + j) * NHEAD + h];
            float a = __expf(lgv - mh);
            sh += a;
            float4 f = *(const float4*)(g_featn + (size_t)sn * HD + c);
            acc.x += a * f.x; acc.y += a * f.y; acc.z += a * f.z; acc.w += a * f.w;
        }
    }
    float inv = 1.0f / sh;
    acc.x *= inv; acc.y *= inv; acc.z *= inv; acc.w *= inv;
    *(float4*)orow = acc;
}

// ---------------- launch ----------------
extern "C" void kernel_launch(void* const* d_in, const int* in_sizes, int n_in,
                              void* d_out, int out_size) {
    const float* feats_node = (const float*)d_in[0];
    const float* feats_edge = (const float*)d_in[1];
    const int*   src        = (const int*)d_in[2];
    const int*   dst        = (const int*)d_in[3];
    const float* W_node     = (const float*)d_in[4];
    const float* attn_l     = (const float*)d_in[5];
    const float* attn_r     = (const float*)d_in[6];
    const float* attn_e     = (const float*)d_in[7];
    float* out = (float*)d_out;

    int gsm = 2 * IN_DIM * GSTR * sizeof(float);        // 135168 B
    static int configured = 0;
    if (!configured) {
        cudaFuncSetAttribute(k_gemm, cudaFuncAttributeMaxDynamicSharedMemorySize, gsm);
        configured = 1;
    }

    k_gemm<<<(N_NODES + 127) / 128, 256, gsm>>>(feats_node, W_node, attn_l, attn_r, dst);
    k_scan<<<NBLK_SCAN, SCAN_BS>>>();
    k_logit<<<(N_EDGES + 255) / 256, 256>>>(feats_edge, src, dst, attn_e);
    k_node<<<(N_NODES * 32 + 255) / 256, 256>>>(out);
}